// round 17
// baseline (speedup 1.0000x reference)
#include <cuda_runtime.h>
#include <cuda_bf16.h>
#include <cuda_fp16.h>
#include <cstdint>

// ---------------- problem constants ----------------
#define BATCH 2
#define SEQ   2048
#define DMODEL 768
#define NHEAD 12
#define HDIM  64
#define STRIDE_ 8
#define QB    128

#define M_TOTAL (BATCH*SEQ)   // 4096
#define K_DIM   DMODEL        // 768
#define N_QKV   (3*DMODEL)    // 2304

// ---------------- device scratch ----------------
__device__ __half g_qkvh[M_TOTAL * N_QKV];
__device__ __half g_ah[M_TOTAL * K_DIM];
__device__ __half g_bh[N_QKV * K_DIM];
__device__ __half g_owh[DMODEL * K_DIM];
__device__ __half g_xh[M_TOTAL * K_DIM];

// ---------------- PTX helpers ----------------
__device__ __forceinline__ uint32_t smem_u32(const void* p) {
    uint32_t a;
    asm("{ .reg .u64 t; cvta.to.shared.u64 t, %1; cvt.u32.u64 %0, t; }" : "=r"(a) : "l"(p));
    return a;
}

#define CP_ASYNC16(dst, src) \
    asm volatile("cp.async.cg.shared.global [%0], [%1], 16;" :: "r"(dst), "l"(src))
#define CP_COMMIT() asm volatile("cp.async.commit_group;" ::: "memory")
#define CP_WAIT2() asm volatile("cp.async.wait_group 2;" ::: "memory")
#define CP_WAIT1() asm volatile("cp.async.wait_group 1;" ::: "memory")
#define CP_WAIT0() asm volatile("cp.async.wait_group 0;" ::: "memory")

#define LDSM_X4(r0, r1, r2, r3, addr) \
    asm volatile("ldmatrix.sync.aligned.m8n8.x4.shared.b16 {%0,%1,%2,%3}, [%4];" \
        : "=r"(r0), "=r"(r1), "=r"(r2), "=r"(r3) : "r"(addr))

#define LDSM_X4_T(r0, r1, r2, r3, addr) \
    asm volatile("ldmatrix.sync.aligned.m8n8.x4.trans.shared.b16 {%0,%1,%2,%3}, [%4];" \
        : "=r"(r0), "=r"(r1), "=r"(r2), "=r"(r3) : "r"(addr))

#define MMA_F16(c, a0, a1, a2, a3, b0, b1) \
    asm("mma.sync.aligned.m16n8k16.row.col.f32.f16.f16.f32 " \
        "{%0,%1,%2,%3}, {%4,%5,%6,%7}, {%8,%9}, {%0,%1,%2,%3};" \
        : "+f"((c)[0]), "+f"((c)[1]), "+f"((c)[2]), "+f"((c)[3]) \
        : "r"(a0), "r"(a1), "r"(a2), "r"(a3), "r"(b0), "r"(b1))

__device__ __forceinline__ uint32_t pack_f16x2(float a, float b) {
    __half2 h = __floats2half2_rn(a, b);
    return *(uint32_t*)&h;
}
__device__ __forceinline__ void store2(float* p, float a, float b) {
    *(float2*)p = make_float2(a, b);
}
__device__ __forceinline__ void store2(__half* p, float a, float b) {
    *(__half2*)p = __floats2half2_rn(a, b);
}

// ---------------- fused fp32 -> fp16 convert ----------------
__global__ __launch_bounds__(256)
void conv_all_kernel(const float* __restrict__ x, const float* __restrict__ w1,
                     const float* __restrict__ w2,
                     __half* __restrict__ xh, __half* __restrict__ bh,
                     __half* __restrict__ owh, int n1, int n2, int n3)
{
    int i = blockIdx.x * 256 + threadIdx.x;
    const float* src;
    __half* dst;
    int off;
    if (i < n1)            { src = x;  dst = xh;  off = i; }
    else if (i < n1 + n2)  { src = w1; dst = bh;  off = i - n1; }
    else if (i < n1+n2+n3) { src = w2; dst = owh; off = i - n1 - n2; }
    else return;
    float4 v = ((const float4*)src)[off];
    __half2 a = __floats2half2_rn(v.x, v.y);
    __half2 b = __floats2half2_rn(v.z, v.w);
    ((uint2*)dst)[off] = make_uint2(*(uint32_t*)&a, *(uint32_t*)&b);
}

// ------- fp16 GEMM 128x128, GBK=64, 3-stage (QKV) -------
#define GBK 64
#define NCHUNK (K_DIM / GBK)          // 12
#define TPAD 72
#define TILE_BYTES (128 * TPAD * 2)   // 18432
#define STAGE_BYTES (2 * TILE_BYTES)  // 36864
#define GEMM_SMEM (3 * STAGE_BYTES)   // 110592 -> 2 CTAs/SM

template <typename OT>
__global__ __launch_bounds__(256, 2)
void gemm_mma_kernel(const __half* __restrict__ A, const __half* __restrict__ B,
                     const float* __restrict__ bias, OT* __restrict__ C, int N)
{
    extern __shared__ char dsm[];
    const uint32_t sbase = smem_u32(dsm);
    const int tid = threadIdx.x;
    const int lane = tid & 31;
    const int wid = tid >> 5;
    const int wm = (wid & 1) * 64;
    const int wn = (wid >> 1) * 32;
    const int bm = blockIdx.y * 128;
    const int bn = blockIdx.x * 128;

    const __half* gp[2] = { A, B };

    float acc[4][4][4];
    #pragma unroll
    for (int i = 0; i < 4; i++)
        #pragma unroll
        for (int j = 0; j < 4; j++)
            #pragma unroll
            for (int r = 0; r < 4; r++) acc[i][j][r] = 0.f;

    auto issue = [&](int stage, int kc) {
        const uint32_t st = sbase + (uint32_t)stage * STAGE_BYTES;
        #pragma unroll
        for (int t = 0; t < 8; ++t) {
            int task = tid + t * 256;
            int tile = task >> 10;
            int idx  = task & 1023;
            int r = idx >> 3, q = idx & 7;
            int row = (tile == 0 ? bm : bn) + r;
            uint32_t dst = st + (uint32_t)tile * TILE_BYTES + (uint32_t)(r * TPAD + q * 8) * 2;
            CP_ASYNC16(dst, gp[tile] + (size_t)row * K_DIM + kc + q * 8);
        }
        CP_COMMIT();
    };

    issue(0, 0);
    issue(1, GBK);
    issue(2, 2 * GBK);

    const int g = lane >> 3;
    const int arow = wm + (g & 1) * 8 + (lane & 7);
    const int acoff = (g >> 1) * 8;
    const int brow0 = wn + (g >> 1) * 8 + (lane & 7);
    const int bcoff = (g & 1) * 8;

    for (int c = 0; c < NCHUNK; ++c) {
        if (c <= NCHUNK - 3)      { CP_WAIT2(); }
        else if (c == NCHUNK - 2) { CP_WAIT1(); }
        else                      { CP_WAIT0(); }
        __syncthreads();

        const uint32_t st = sbase + (uint32_t)(c % 3) * STAGE_BYTES;
        const uint32_t aT = st;
        const uint32_t bT = st + TILE_BYTES;

        #pragma unroll
        for (int ks = 0; ks < 4; ++ks) {
            const int acol = ks * 16 + acoff;
            const int bcol = ks * 16 + bcoff;
            uint32_t a[4][4];
            #pragma unroll
            for (int mf = 0; mf < 4; ++mf) {
                uint32_t off = (uint32_t)((arow + mf * 16) * TPAD + acol) * 2;
                LDSM_X4(a[mf][0], a[mf][1], a[mf][2], a[mf][3], aT + off);
            }
            #pragma unroll
            for (int nf2 = 0; nf2 < 2; ++nf2) {
                uint32_t off = (uint32_t)((brow0 + nf2 * 16) * TPAD + bcol) * 2;
                uint32_t bf[2][2];
                LDSM_X4(bf[0][0], bf[0][1], bf[1][0], bf[1][1], bT + off);
                #pragma unroll
                for (int mf = 0; mf < 4; ++mf)
                    #pragma unroll
                    for (int q = 0; q < 2; ++q)
                        MMA_F16(acc[mf][2 * nf2 + q], a[mf][0], a[mf][1], a[mf][2], a[mf][3],
                                bf[q][0], bf[q][1]);
            }
        }
        __syncthreads();
        if (c + 3 < NCHUNK) issue(c % 3, (c + 3) * GBK);
    }

    #pragma unroll
    for (int mf = 0; mf < 4; ++mf) {
        const int m = bm + wm + mf * 16 + (lane >> 2);
        #pragma unroll
        for (int nf = 0; nf < 4; ++nf) {
            const int n = bn + wn + nf * 8 + (lane & 3) * 2;
            const float2 bv = *(const float2*)&bias[n];
            store2(&C[(size_t)m * N + n],       acc[mf][nf][0] + bv.x, acc[mf][nf][1] + bv.y);
            store2(&C[(size_t)(m + 8) * N + n], acc[mf][nf][2] + bv.x, acc[mf][nf][3] + bv.y);
        }
    }
}

// ------- fp16 GEMM 64x128, GBK=128, 2-stage (proj: high MMA density) -------
#define GBK2 128
#define NCHUNK2 (K_DIM / GBK2)        // 6
#define TPAD2 136                      // 272 B rows (272 mod 128 = 16 -> conflict-free)
#define A2_TILE (64 * TPAD2 * 2)       // 17408
#define B2_TILE (128 * TPAD2 * 2)      // 34816
#define STAGE2  (A2_TILE + B2_TILE)    // 52224
#define GEMM64_SMEM (2 * STAGE2)       // 104448 -> 2 CTAs/SM

__global__ __launch_bounds__(256, 2)
void gemm_mma64_kernel(const __half* __restrict__ A, const __half* __restrict__ B,
                       const float* __restrict__ bias, float* __restrict__ C, int N)
{
    extern __shared__ char dsm[];
    const uint32_t sbase = smem_u32(dsm);
    const int tid = threadIdx.x;
    const int lane = tid & 31;
    const int wid = tid >> 5;
    const int wm = (wid & 1) * 32;
    const int wn = (wid >> 1) * 32;
    const int bm = blockIdx.y * 64;
    const int bn = blockIdx.x * 128;

    float acc[2][4][4];
    #pragma unroll
    for (int i = 0; i < 2; i++)
        #pragma unroll
        for (int j = 0; j < 4; j++)
            #pragma unroll
            for (int r = 0; r < 4; r++) acc[i][j][r] = 0.f;

    auto issue = [&](int stage, int kc) {
        const uint32_t st = sbase + (uint32_t)stage * STAGE2;
        #pragma unroll
        for (int t = 0; t < 12; ++t) {
            int task = tid + t * 256;          // 0..3071
            int tile, idx;
            if (task < 1024) { tile = 0; idx = task; }
            else             { tile = 1; idx = task - 1024; }
            int r = idx >> 4, q = idx & 15;
            int row = (tile == 0 ? bm : bn) + r;
            uint32_t dst = st + (tile ? A2_TILE : 0u) + (uint32_t)(r * TPAD2 + q * 8) * 2;
            CP_ASYNC16(dst, (tile == 0 ? A : B) + (size_t)row * K_DIM + kc + q * 8);
        }
        CP_COMMIT();
    };

    issue(0, 0);
    issue(1, GBK2);

    const int g = lane >> 3;
    const int arow = wm + (g & 1) * 8 + (lane & 7);
    const int acoff = (g >> 1) * 8;
    const int brow0 = wn + (g >> 1) * 8 + (lane & 7);
    const int bcoff = (g & 1) * 8;

    for (int c = 0; c < NCHUNK2; ++c) {
        if (c + 1 < NCHUNK2) { CP_WAIT1(); } else { CP_WAIT0(); }
        __syncthreads();

        const uint32_t st = sbase + (uint32_t)(c & 1) * STAGE2;
        const uint32_t aT = st;
        const uint32_t bT = st + A2_TILE;

        #pragma unroll
        for (int ks = 0; ks < 8; ++ks) {
            const int acol = ks * 16 + acoff;
            const int bcol = ks * 16 + bcoff;
            uint32_t a[2][4];
            #pragma unroll
            for (int mf = 0; mf < 2; ++mf) {
                uint32_t off = (uint32_t)((arow + mf * 16) * TPAD2 + acol) * 2;
                LDSM_X4(a[mf][0], a[mf][1], a[mf][2], a[mf][3], aT + off);
            }
            #pragma unroll
            for (int nf2 = 0; nf2 < 2; ++nf2) {
                uint32_t off = (uint32_t)((brow0 + nf2 * 16) * TPAD2 + bcol) * 2;
                uint32_t bf[2][2];
                LDSM_X4(bf[0][0], bf[0][1], bf[1][0], bf[1][1], bT + off);
                #pragma unroll
                for (int mf = 0; mf < 2; ++mf)
                    #pragma unroll
                    for (int q = 0; q < 2; ++q)
                        MMA_F16(acc[mf][2 * nf2 + q], a[mf][0], a[mf][1], a[mf][2], a[mf][3],
                                bf[q][0], bf[q][1]);
            }
        }
        __syncthreads();
        if (c + 2 < NCHUNK2) issue(c & 1, (c + 2) * GBK2);
    }

    #pragma unroll
    for (int mf = 0; mf < 2; ++mf) {
        const int m = bm + wm + mf * 16 + (lane >> 2);
        #pragma unroll
        for (int nf = 0; nf < 4; ++nf) {
            const int n = bn + wn + nf * 8 + (lane & 3) * 2;
            const float2 bv = *(const float2*)&bias[n];
            store2(&C[(size_t)m * N + n],       acc[mf][nf][0] + bv.x, acc[mf][nf][1] + bv.y);
            store2(&C[(size_t)(m + 8) * N + n], acc[mf][nf][2] + bv.x, acc[mf][nf][3] + bv.y);
        }
    }
}

// ==== MMA flash attention: all-fp16 single-product, band fused via MMA ====
#define TROWB 144
#define AT_K  0
#define AT_V  36864
#define AT_Q  73728
#define ATTN_SMEM 92160

__global__ __launch_bounds__(256, 2)
void attn_mma_kernel(const __half* __restrict__ qkvh, __half* __restrict__ oh)
{
    extern __shared__ char smraw[];
    const uint32_t sb = smem_u32(smraw);
    const int tid = threadIdx.x;
    const int lane = tid & 31;
    const int w = tid >> 5;

    const int bh = blockIdx.y;
    const int b = bh / NHEAD;
    const int h = bh % NHEAD;
    const int qb = gridDim.x - 1 - blockIdx.x;
    const int q0 = qb * QB;
    const int n_str = 16 * (qb + 1);
    const int n_pad = (n_str + 63) & ~63;
    const __half2 hscale = __float2half2_rn(0.125f);

    // Phase A: local band
    for (int task = tid; task < 144 * 16; task += 256) {
        const int lrow = task >> 4;
        const int sel  = (task >> 3) & 1;
        const int d8   = (task & 7) << 3;
        const int j    = q0 - 16 + lrow;
        uint4 pk = make_uint4(0, 0, 0, 0);
        if (j >= 0) {
            const size_t src = (size_t)(b * SEQ + j) * (3 * DMODEL)
                             + (size_t)(1 + sel) * DMODEL + h * HDIM + d8;
            pk = *(const uint4*)&qkvh[src];
        }
        *(uint4*)(smraw + (sel ? AT_V : AT_K) + lrow * TROWB + d8 * 2) = pk;
    }
    for (int task = tid; task < 128 * 8; task += 256) {
        const int r  = task >> 3;
        const int d8 = (task & 7) << 3;
        const size_t src = (size_t)(b * SEQ + q0 + r) * (3 * DMODEL) + h * HDIM + d8;
        uint4 v = *(const uint4*)&qkvh[src];
        __half2* pv = (__half2*)&v;
        #pragma unroll
        for (int k = 0; k < 4; ++k) pv[k] = __hmul2(pv[k], hscale);
        *(uint4*)(smraw + AT_Q + r * TROWB + d8 * 2) = v;
    }
    __syncthreads();

    const int g = lane >> 3;
    const int tig = lane & 3;
    const int arow = 16 * w + (g & 1) * 8 + (lane & 7);
    const int acoff = (g >> 1) * 8;
    uint32_t qf[4][4];
    #pragma unroll
    for (int kd = 0; kd < 4; ++kd) {
        const uint32_t off = (uint32_t)(arow * TROWB + (kd * 16 + acoff) * 2);
        LDSM_X4(qf[kd][0], qf[kd][1], qf[kd][2], qf[kd][3], sb + AT_Q + off);
    }

    float ofr[8][4];
    #pragma unroll
    for (int i = 0; i < 8; i++) { ofr[i][0]=0.f; ofr[i][1]=0.f; ofr[i][2]=0.f; ofr[i][3]=0.f; }
    float m0 = -1e30f, m1 = -1e30f, l0 = 0.f, l1 = 0.f;

    const int skrow = (g >> 1) * 8 + (lane & 7);
    const int sdcol = (g & 1) * 8;
    const int vkrow = (g & 1) * 8 + (lane & 7);
    const int vdcol = (g >> 1) * 8;
    const int qrow = lane >> 2;

    // band S2
    {
        const int lbase = 16 * w;
        float sfr[4][4];
        #pragma unroll
        for (int i = 0; i < 4; i++) { sfr[i][0]=0.f; sfr[i][1]=0.f; sfr[i][2]=0.f; sfr[i][3]=0.f; }

        #pragma unroll
        for (int kd = 0; kd < 4; ++kd) {
            #pragma unroll
            for (int kg = 0; kg < 2; ++kg) {
                const uint32_t addr = sb + AT_K +
                    (uint32_t)((lbase + kg * 16 + skrow) * TROWB + (kd * 16 + sdcol) * 2);
                uint32_t kf[4];
                LDSM_X4(kf[0], kf[1], kf[2], kf[3], addr);
                MMA_F16(sfr[2*kg],   qf[kd][0], qf[kd][1], qf[kd][2], qf[kd][3], kf[0], kf[1]);
                MMA_F16(sfr[2*kg+1], qf[kd][0], qf[kd][1], qf[kd][2], qf[kd][3], kf[2], kf[3]);
            }
        }

        const int j0 = q0 + 16 * w - 16;
        float mx0 = -1e30f, mx1 = -1e30f;
        #pragma unroll
        for (int nf = 0; nf < 4; ++nf) {
            #pragma unroll
            for (int r = 0; r < 2; ++r) {
                const int c = nf * 8 + 2 * tig + r;
                const int j = j0 + c;
                const bool ok = (((j & 7) != 0) && (j >= 0));
                const bool v0 = ok && (c == qrow + 16 || c == qrow + 15);
                const bool v1 = ok && (c == qrow + 24 || c == qrow + 23);
                if (!v0) sfr[nf][r]     = -1e30f;
                if (!v1) sfr[nf][r + 2] = -1e30f;
            }
            mx0 = fmaxf(mx0, fmaxf(sfr[nf][0], sfr[nf][1]));
            mx1 = fmaxf(mx1, fmaxf(sfr[nf][2], sfr[nf][3]));
        }
        mx0 = fmaxf(mx0, __shfl_xor_sync(0xFFFFFFFFu, mx0, 1));
        mx0 = fmaxf(mx0, __shfl_xor_sync(0xFFFFFFFFu, mx0, 2));
        mx1 = fmaxf(mx1, __shfl_xor_sync(0xFFFFFFFFu, mx1, 1));
        mx1 = fmaxf(mx1, __shfl_xor_sync(0xFFFFFFFFu, mx1, 2));
        const float mn0 = fmaxf(fmaxf(m0, mx0), -1e29f);
        const float mn1 = fmaxf(fmaxf(m1, mx1), -1e29f);
        float s0 = 0.f, s1 = 0.f;
        #pragma unroll
        for (int nf = 0; nf < 4; ++nf) {
            sfr[nf][0] = __expf(sfr[nf][0] - mn0);
            sfr[nf][1] = __expf(sfr[nf][1] - mn0);
            sfr[nf][2] = __expf(sfr[nf][2] - mn1);
            sfr[nf][3] = __expf(sfr[nf][3] - mn1);
            s0 += sfr[nf][0] + sfr[nf][1];
            s1 += sfr[nf][2] + sfr[nf][3];
        }
        s0 += __shfl_xor_sync(0xFFFFFFFFu, s0, 1);
        s0 += __shfl_xor_sync(0xFFFFFFFFu, s0, 2);
        s1 += __shfl_xor_sync(0xFFFFFFFFu, s1, 1);
        s1 += __shfl_xor_sync(0xFFFFFFFFu, s1, 2);
        l0 = s0; l1 = s1;
        m0 = mn0; m1 = mn1;

        uint32_t ph[2][4];
        #pragma unroll
        for (int kk = 0; kk < 2; ++kk) {
            ph[kk][0] = pack_f16x2(sfr[2*kk][0],   sfr[2*kk][1]);
            ph[kk][1] = pack_f16x2(sfr[2*kk][2],   sfr[2*kk][3]);
            ph[kk][2] = pack_f16x2(sfr[2*kk+1][0], sfr[2*kk+1][1]);
            ph[kk][3] = pack_f16x2(sfr[2*kk+1][2], sfr[2*kk+1][3]);
        }
        #pragma unroll
        for (int kk = 0; kk < 2; ++kk) {
            #pragma unroll
            for (int dd = 0; dd < 4; ++dd) {
                const uint32_t addr = sb + AT_V +
                    (uint32_t)((lbase + kk * 16 + vkrow) * TROWB + (dd * 16 + vdcol) * 2);
                uint32_t vf[4];
                LDSM_X4_T(vf[0], vf[1], vf[2], vf[3], addr);
                MMA_F16(ofr[2*dd],   ph[kk][0], ph[kk][1], ph[kk][2], ph[kk][3], vf[0], vf[1]);
                MMA_F16(ofr[2*dd+1], ph[kk][0], ph[kk][1], ph[kk][2], ph[kk][3], vf[2], vf[3]);
            }
        }
    }

    // Phase B: strided K/V
    __syncthreads();
    for (int task = tid; task < n_str * 16; task += 256) {
        const int t   = task >> 4;
        const int sel = (task >> 3) & 1;
        const int d8  = (task & 7) << 3;
        const size_t src = (size_t)(b * SEQ + t * STRIDE_) * (3 * DMODEL)
                         + (size_t)(1 + sel) * DMODEL + h * HDIM + d8;
        *(uint4*)(smraw + (sel ? AT_V : AT_K) + t * TROWB + d8 * 2) =
            *(const uint4*)&qkvh[src];
    }
    for (int task = tid; task < (n_pad - n_str) * 8; task += 256) {
        const int t  = n_str + (task >> 3);
        const int d8 = (task & 7) << 3;
        const uint4 z = make_uint4(0, 0, 0, 0);
        *(uint4*)(smraw + AT_K + t * TROWB + d8 * 2) = z;
        *(uint4*)(smraw + AT_V + t * TROWB + d8 * 2) = z;
    }
    __syncthreads();

    const int row0q = q0 + 16 * w + qrow;
    const int nt0 = (row0q >> 3) + 1;
    const int nt1 = ((row0q + 8) >> 3) + 1;
    const int nchunks = (16 * qb + 2 * w + 2 + 63) >> 6;

    for (int ch = 0; ch < nchunks; ++ch) {
        const int c0 = ch * 64;
        float sfr[8][4];
        #pragma unroll
        for (int i = 0; i < 8; i++) { sfr[i][0]=0.f; sfr[i][1]=0.f; sfr[i][2]=0.f; sfr[i][3]=0.f; }

        #pragma unroll
        for (int kd = 0; kd < 4; ++kd) {
            #pragma unroll
            for (int kg = 0; kg < 4; ++kg) {
                const uint32_t addr = sb + AT_K +
                    (uint32_t)((c0 + kg * 16 + skrow) * TROWB + (kd * 16 + sdcol) * 2);
                uint32_t kf[4];
                LDSM_X4(kf[0], kf[1], kf[2], kf[3], addr);
                MMA_F16(sfr[2*kg],   qf[kd][0], qf[kd][1], qf[kd][2], qf[kd][3], kf[0], kf[1]);
                MMA_F16(sfr[2*kg+1], qf[kd][0], qf[kd][1], qf[kd][2], qf[kd][3], kf[2], kf[3]);
            }
        }

        float mx0 = -1e30f, mx1 = -1e30f;
        #pragma unroll
        for (int nf = 0; nf < 8; ++nf) {
            const int tb = c0 + nf * 8 + 2 * tig;
            if (tb >= nt0)     sfr[nf][0] = -1e30f;
            if (tb + 1 >= nt0) sfr[nf][1] = -1e30f;
            if (tb >= nt1)     sfr[nf][2] = -1e30f;
            if (tb + 1 >= nt1) sfr[nf][3] = -1e30f;
            mx0 = fmaxf(mx0, fmaxf(sfr[nf][0], sfr[nf][1]));
            mx1 = fmaxf(mx1, fmaxf(sfr[nf][2], sfr[nf][3]));
        }
        mx0 = fmaxf(mx0, __shfl_xor_sync(0xFFFFFFFFu, mx0, 1));
        mx0 = fmaxf(mx0, __shfl_xor_sync(0xFFFFFFFFu, mx0, 2));
        mx1 = fmaxf(mx1, __shfl_xor_sync(0xFFFFFFFFu, mx1, 1));
        mx1 = fmaxf(mx1, __shfl_xor_sync(0xFFFFFFFFu, mx1, 2));
        const float mn0 = fmaxf(m0, mx0);
        const float mn1 = fmaxf(m1, mx1);
        const float al0 = __expf(m0 - mn0);
        const float al1 = __expf(m1 - mn1);
        float s0 = 0.f, s1 = 0.f;
        #pragma unroll
        for (int nf = 0; nf < 8; ++nf) {
            sfr[nf][0] = __expf(sfr[nf][0] - mn0);
            sfr[nf][1] = __expf(sfr[nf][1] - mn0);
            sfr[nf][2] = __expf(sfr[nf][2] - mn1);
            sfr[nf][3] = __expf(sfr[nf][3] - mn1);
            s0 += sfr[nf][0] + sfr[nf][1];
            s1 += sfr[nf][2] + sfr[nf][3];
        }
        s0 += __shfl_xor_sync(0xFFFFFFFFu, s0, 1);
        s0 += __shfl_xor_sync(0xFFFFFFFFu, s0, 2);
        s1 += __shfl_xor_sync(0xFFFFFFFFu, s1, 1);
        s1 += __shfl_xor_sync(0xFFFFFFFFu, s1, 2);
        l0 = l0 * al0 + s0;
        l1 = l1 * al1 + s1;
        m0 = mn0; m1 = mn1;
        #pragma unroll
        for (int nf = 0; nf < 8; ++nf) {
            ofr[nf][0] *= al0; ofr[nf][1] *= al0;
            ofr[nf][2] *= al1; ofr[nf][3] *= al1;
        }

        uint32_t ph[4][4];
        #pragma unroll
        for (int kk = 0; kk < 4; ++kk) {
            ph[kk][0] = pack_f16x2(sfr[2*kk][0],   sfr[2*kk][1]);
            ph[kk][1] = pack_f16x2(sfr[2*kk][2],   sfr[2*kk][3]);
            ph[kk][2] = pack_f16x2(sfr[2*kk+1][0], sfr[2*kk+1][1]);
            ph[kk][3] = pack_f16x2(sfr[2*kk+1][2], sfr[2*kk+1][3]);
        }
        #pragma unroll
        for (int kk = 0; kk < 4; ++kk) {
            #pragma unroll
            for (int dd = 0; dd < 4; ++dd) {
                const uint32_t addr = sb + AT_V +
                    (uint32_t)((c0 + kk * 16 + vkrow) * TROWB + (dd * 16 + vdcol) * 2);
                uint32_t vf[4];
                LDSM_X4_T(vf[0], vf[1], vf[2], vf[3], addr);
                MMA_F16(ofr[2*dd],   ph[kk][0], ph[kk][1], ph[kk][2], ph[kk][3], vf[0], vf[1]);
                MMA_F16(ofr[2*dd+1], ph[kk][0], ph[kk][1], ph[kk][2], ph[kk][3], vf[2], vf[3]);
            }
        }
    }

    // normalize + coalesced write
    const float inv0 = 1.f / l0;
    const float inv1 = 1.f / l1;
    __syncthreads();
    {
        const int r0 = 16 * w + qrow;
        #pragma unroll
        for (int nf = 0; nf < 8; ++nf) {
            const int colb = (nf * 8 + 2 * tig) * 2;
            *(__half2*)(smraw + AT_K + r0 * TROWB + colb) =
                __floats2half2_rn(ofr[nf][0] * inv0, ofr[nf][1] * inv0);
            *(__half2*)(smraw + AT_K + (r0 + 8) * TROWB + colb) =
                __floats2half2_rn(ofr[nf][2] * inv1, ofr[nf][3] * inv1);
        }
    }
    __syncwarp();
    #pragma unroll
    for (int t = 0; t < 4; ++t) {
        const int task = lane + t * 32;
        const int r16 = task >> 3;
        const int q = task & 7;
        const int srow = 16 * w + r16;
        const uint4 v = *(const uint4*)(smraw + AT_K + srow * TROWB + q * 16);
        const size_t ob = (size_t)(b * SEQ + q0 + srow) * DMODEL + h * HDIM + q * 8;
        *(uint4*)&oh[ob] = v;
    }
}

// ---------------- launcher ----------------
extern "C" void kernel_launch(void* const* d_in, const int* in_sizes, int n_in,
                              void* d_out, int out_size)
{
    const float* x      = (const float*)d_in[0];
    const float* qkv_w  = (const float*)d_in[1];
    const float* qkv_b  = (const float*)d_in[2];
    const float* out_w  = (const float*)d_in[3];
    const float* out_b  = (const float*)d_in[4];
    float* out = (float*)d_out;

    __half *qkvh, *ah, *bh, *owh, *xh;
    cudaGetSymbolAddress((void**)&qkvh, g_qkvh);
    cudaGetSymbolAddress((void**)&ah,   g_ah);
    cudaGetSymbolAddress((void**)&bh,   g_bh);
    cudaGetSymbolAddress((void**)&owh,  g_owh);
    cudaGetSymbolAddress((void**)&xh,   g_xh);

    cudaFuncSetAttribute(gemm_mma_kernel<__half>,
                         cudaFuncAttributeMaxDynamicSharedMemorySize, GEMM_SMEM);
    cudaFuncSetAttribute(gemm_mma64_kernel,
                         cudaFuncAttributeMaxDynamicSharedMemorySize, GEMM64_SMEM);
    cudaFuncSetAttribute(attn_mma_kernel,
                         cudaFuncAttributeMaxDynamicSharedMemorySize, ATTN_SMEM);

    // fused fp16 conversions (one launch)
    {
        const int n1 = M_TOTAL * K_DIM / 4;
        const int n2 = N_QKV * K_DIM / 4;
        const int n3 = DMODEL * K_DIM / 4;
        const int nt = n1 + n2 + n3;
        conv_all_kernel<<<(nt + 255) / 256, 256>>>(x, qkv_w, out_w, xh, bh, owh, n1, n2, n3);
    }

    // 1) QKV projection -> fp16 (128x128 tiles, GBK=64, 3-stage)
    gemm_mma_kernel<__half><<<dim3(N_QKV / 128, M_TOTAL / 128), 256, GEMM_SMEM>>>(
        xh, bh, qkv_b, qkvh, N_QKV);

    // 2) strided attention
    attn_mma_kernel<<<dim3(SEQ / QB, BATCH * NHEAD), 256, ATTN_SMEM>>>(qkvh, ah);

    // 3) output projection -> fp32 (64x128 tiles, GBK=128, 2-stage, 384 CTAs)
    gemm_mma64_kernel<<<dim3(DMODEL / 128, M_TOTAL / 64), 256, GEMM64_SMEM>>>(
        ah, owh, out_b, out, DMODEL);
}